// round 4
// baseline (speedup 1.0000x reference)
#include <cuda_runtime.h>

#define NSAMP 16
#define CH 64
#define CWD 8
#define EPS 1e-5f
#define MAXN 100000

#define G1 1024
#define G2 1184
#define G3 1184
#define GF 1184

typedef unsigned long long u64;

// ---------------- f32x2 helpers (sm_100+) ----------------
__device__ __forceinline__ u64 pk2(float lo, float hi) {
    u64 r; asm("mov.b64 %0,{%1,%2};" : "=l"(r) : "f"(lo), "f"(hi)); return r;
}
__device__ __forceinline__ float2 upk2(u64 v) {
    float2 f; asm("mov.b64 {%0,%1},%2;" : "=f"(f.x), "=f"(f.y) : "l"(v)); return f;
}
__device__ __forceinline__ u64 ffma2(u64 a, u64 b, u64 c) {
    u64 d; asm("fma.rn.f32x2 %0,%1,%2,%3;" : "=l"(d) : "l"(a), "l"(b), "l"(c)); return d;
}
__device__ __forceinline__ u64 fadd2(u64 a, u64 b) {
    u64 d; asm("add.rn.f32x2 %0,%1,%2;" : "=l"(d) : "l"(a), "l"(b)); return d;
}

// ---------------- device scratch ----------------
__device__ float g_xq[MAXN * CH];
__device__ float g_xk[MAXN * CH];
__device__ float g_xv[MAXN * CH];
__device__ float g_pr0[MAXN * NSAMP * 3];
__device__ float g_T[MAXN * NSAMP * 3];
__device__ float g_w1[MAXN * NSAMP * CWD];

__device__ float g_part1[G1 * 9];
__device__ float g_part2[G2 * 128];
__device__ float g_part3[G3 * 16];

__device__ float g_E[9];
__device__ float g_be[3];
__device__ float g_s2[CH];
__device__ float g_b2[CH];
__device__ float g_s3[CWD];
__device__ float g_b3[CWD];

// ---------------- kernel 1: q/k/v GEMMs (f32x2) ----------------
__global__ __launch_bounds__(256) void k_qkv(
    const float* __restrict__ x,
    const float* __restrict__ Wq, const float* __restrict__ bq,
    const float* __restrict__ Wk, const float* __restrict__ bk,
    const float* __restrict__ Wv, const float* __restrict__ bv,
    int n)
{
    __shared__ __align__(16) float sW[CH * CH];
    __shared__ __align__(16) float sb[CH];
    int tid = threadIdx.x;
    int pt  = blockIdx.x * 256 + tid;
    bool valid = pt < n;

    float xr[CH];
    if (valid) {
        const float4* xp = reinterpret_cast<const float4*>(x + (size_t)pt * CH);
        #pragma unroll
        for (int i = 0; i < 16; i++) {
            float4 v = xp[i];
            xr[4*i+0] = v.x; xr[4*i+1] = v.y; xr[4*i+2] = v.z; xr[4*i+3] = v.w;
        }
    }

    for (int m = 0; m < 3; m++) {
        const float* W = (m == 0) ? Wq : (m == 1) ? Wk : Wv;
        const float* b = (m == 0) ? bq : (m == 1) ? bk : bv;
        float* outp    = (m == 0) ? g_xq : (m == 1) ? g_xk : g_xv;

        for (int i = tid; i < CH * CH / 4; i += 256)
            reinterpret_cast<float4*>(sW)[i] = reinterpret_cast<const float4*>(W)[i];
        if (tid < CH) sb[tid] = b[tid];
        __syncthreads();

        if (valid) {
            #pragma unroll
            for (int chnk = 0; chnk < 2; chnk++) {
                int c0 = chnk * 32;
                u64 acc[16];
                const u64* sbp = reinterpret_cast<const u64*>(&sb[c0]);
                #pragma unroll
                for (int i = 0; i < 16; i++) acc[i] = sbp[i];
                #pragma unroll 4
                for (int k = 0; k < CH; k++) {
                    u64 xk2 = pk2(xr[k], xr[k]);
                    const ulonglong2* wr = reinterpret_cast<const ulonglong2*>(&sW[k * CH + c0]);
                    #pragma unroll
                    for (int cc = 0; cc < 8; cc++) {
                        ulonglong2 w2 = wr[cc];
                        acc[2*cc+0] = ffma2(xk2, w2.x, acc[2*cc+0]);
                        acc[2*cc+1] = ffma2(xk2, w2.y, acc[2*cc+1]);
                    }
                }
                ulonglong2* op = reinterpret_cast<ulonglong2*>(outp + (size_t)pt * CH + c0);
                #pragma unroll
                for (int cc = 0; cc < 8; cc++)
                    op[cc] = make_ulonglong2(acc[2*cc+0], acc[2*cc+1]);
            }
        }
        __syncthreads();
    }
}

// ---------------- kernel 2: mean/cov of p_r0 + materialize p_r0 ----------------
__global__ __launch_bounds__(256) void k_stats1(
    const float* __restrict__ p, const int* __restrict__ idx, int n)
{
    float a[9];
    #pragma unroll
    for (int i = 0; i < 9; i++) a[i] = 0.f;

    int total = n * NSAMP;
    for (int e = blockIdx.x * blockDim.x + threadIdx.x; e < total;
         e += gridDim.x * blockDim.x) {
        int pt = e >> 4;
        int j  = idx[e];
        float dx = p[j*3+0] - p[pt*3+0];
        float dy = p[j*3+1] - p[pt*3+1];
        float dz = p[j*3+2] - p[pt*3+2];
        g_pr0[e*3+0] = dx; g_pr0[e*3+1] = dy; g_pr0[e*3+2] = dz;
        a[0] += dx;     a[1] += dy;     a[2] += dz;
        a[3] += dx*dx;  a[4] += dy*dy;  a[5] += dz*dz;
        a[6] += dx*dy;  a[7] += dx*dz;  a[8] += dy*dz;
    }

    __shared__ float sm[9][256];
    int tid = threadIdx.x;
    #pragma unroll
    for (int i = 0; i < 9; i++) sm[i][tid] = a[i];
    __syncthreads();
    for (int s = 128; s > 0; s >>= 1) {
        if (tid < s) {
            #pragma unroll
            for (int i = 0; i < 9; i++) sm[i][tid] += sm[i][tid + s];
        }
        __syncthreads();
    }
    if (tid < 9) g_part1[blockIdx.x * 9 + tid] = sm[tid][0];
}

// ---------------- finalize 1 ----------------
__global__ __launch_bounds__(256) void k_fin1(
    const float* __restrict__ Wp1, const float* __restrict__ bp1,
    const float* __restrict__ gp,  const float* __restrict__ betap, int n)
{
    __shared__ float ssum[9][16];
    int tid = threadIdx.x;
    if (tid < 144) {
        int q = tid / 16, s = tid % 16;
        float a = 0.f;
        for (int b = s; b < G1; b += 16) a += g_part1[b * 9 + q];
        ssum[q][s] = a;
    }
    __syncthreads();
    if (tid == 0) {
        float S[9];
        #pragma unroll
        for (int q = 0; q < 9; q++) {
            float a = 0.f;
            for (int s = 0; s < 16; s++) a += ssum[q][s];
            S[q] = a;
        }
        float M  = (float)n * NSAMP;
        float m0 = S[0]/M, m1 = S[1]/M, m2 = S[2]/M;
        float C00 = S[3]/M - m0*m0, C11 = S[4]/M - m1*m1, C22 = S[5]/M - m2*m2;
        float C01 = S[6]/M - m0*m1, C02 = S[7]/M - m0*m2, C12 = S[8]/M - m1*m2;
        for (int j = 0; j < 3; j++) {
            float w0 = Wp1[0*3+j], w1 = Wp1[1*3+j], w2 = Wp1[2*3+j];
            float mean = m0*w0 + m1*w1 + m2*w2 + bp1[j];
            float var  = w0*w0*C00 + w1*w1*C11 + w2*w2*C22
                       + 2.f*(w0*w1*C01 + w0*w2*C02 + w1*w2*C12);
            float sc = gp[j] * rsqrtf(var + EPS);
            g_E[0*3+j] = w0 * sc;
            g_E[1*3+j] = w1 * sc;
            g_E[2*3+j] = w2 * sc;
            g_be[j] = (bp1[j] - mean) * sc + betap[j];
        }
    }
}

// ---------------- kernel 3: stats of r_qk + compute/store T (fused) ----------------
__global__ __launch_bounds__(256, 3) void k_stats2(
    const int* __restrict__ idx,
    const float* __restrict__ Wp2, const float* __restrict__ bp2, int n)
{
    __shared__ float sT[8][48];
    int tid = threadIdx.x;
    int l = tid & 31, w = tid >> 5;
    int c0 = 2 * l;

    float E[9], be[3];
    #pragma unroll
    for (int i = 0; i < 9; i++) E[i] = g_E[i];
    #pragma unroll
    for (int i = 0; i < 3; i++) be[i] = g_be[i];

    u64 w20 = *reinterpret_cast<const u64*>(Wp2 + 0*CH + c0);
    u64 w21 = *reinterpret_cast<const u64*>(Wp2 + 1*CH + c0);
    u64 w22 = *reinterpret_cast<const u64*>(Wp2 + 2*CH + c0);
    float2 b2p = *reinterpret_cast<const float2*>(bp2 + c0);

    u64 sacc = 0ull, qacc = 0ull;
    int warpsTotal = gridDim.x * 8;
    for (int pt = blockIdx.x * 8 + w; pt < n; pt += warpsTotal) {
        // issue the 16 gathers first (max MLP)
        int jarr[NSAMP];
        {
            const int4* ip4 = reinterpret_cast<const int4*>(idx + pt * NSAMP);
            #pragma unroll
            for (int t4 = 0; t4 < 4; t4++) {
                int4 v = ip4[t4];
                jarr[t4*4+0] = v.x; jarr[t4*4+1] = v.y; jarr[t4*4+2] = v.z; jarr[t4*4+3] = v.w;
            }
        }
        u64 pre[NSAMP];
        #pragma unroll
        for (int t = 0; t < NSAMP; t++)
            pre[t] = *reinterpret_cast<const u64*>(g_xk + (size_t)jarr[t] * CH + c0);

        float2 xq = *reinterpret_cast<const float2*>(g_xq + (size_t)pt * CH + c0);
        u64 base2 = pk2(b2p.x - xq.x, b2p.y - xq.y);

        // compute T from pr0 (overlapped under the gathers), store smem + gmem
        if (l < NSAMP) {
            size_t e = (size_t)pt * NSAMP + l;
            float dx = g_pr0[e*3+0], dy = g_pr0[e*3+1], dz = g_pr0[e*3+2];
            float t0 = fmaxf(0.f, dx*E[0] + dy*E[3] + dz*E[6] + be[0]);
            float t1 = fmaxf(0.f, dx*E[1] + dy*E[4] + dz*E[7] + be[1]);
            float t2 = fmaxf(0.f, dx*E[2] + dy*E[5] + dz*E[8] + be[2]);
            sT[w][l*3+0] = t0; sT[w][l*3+1] = t1; sT[w][l*3+2] = t2;
            g_T[e*3+0] = t0; g_T[e*3+1] = t1; g_T[e*3+2] = t2;
        }
        __syncwarp();
        const float* tp = &sT[w][0];
        #pragma unroll
        for (int t = 0; t < NSAMP; t++) {
            u64 acc = base2;
            acc = ffma2(pk2(tp[3*t+0], tp[3*t+0]), w20, acc);
            acc = ffma2(pk2(tp[3*t+1], tp[3*t+1]), w21, acc);
            acc = ffma2(pk2(tp[3*t+2], tp[3*t+2]), w22, acc);
            u64 r2 = fadd2(pre[t], acc);
            sacc = fadd2(sacc, r2);
            qacc = ffma2(r2, r2, qacc);
        }
        __syncwarp();
    }

    __shared__ float ss[8][64], sq[8][64];
    float2 sf = upk2(sacc), qf = upk2(qacc);
    ss[w][c0] = sf.x; ss[w][c0+1] = sf.y;
    sq[w][c0] = qf.x; sq[w][c0+1] = qf.y;
    __syncthreads();
    if (tid < 64) {
        float a = 0.f, b = 0.f;
        #pragma unroll
        for (int ww = 0; ww < 8; ww++) { a += ss[ww][tid]; b += sq[ww][tid]; }
        g_part2[blockIdx.x * 128 + tid]      = a;
        g_part2[blockIdx.x * 128 + 64 + tid] = b;
    }
}

// ---------------- finalize 2 ----------------
__global__ __launch_bounds__(512) void k_fin2(
    const float* __restrict__ gw1, const float* __restrict__ bw1, int n)
{
    __shared__ float acc[4][128];
    int tid = threadIdx.x;
    int q = tid & 127, s = tid >> 7;
    float a = 0.f;
    for (int b = s; b < G2; b += 4) a += g_part2[b * 128 + q];
    acc[s][q] = a;
    __syncthreads();
    if (tid < 64) {
        float sum = acc[0][tid] + acc[1][tid] + acc[2][tid] + acc[3][tid];
        float ssq = acc[0][64+tid] + acc[1][64+tid] + acc[2][64+tid] + acc[3][64+tid];
        float M = (float)n * NSAMP;
        float mean = sum / M;
        float var  = ssq / M - mean * mean;
        float sc = gw1[tid] * rsqrtf(var + EPS);
        g_s2[tid] = sc;
        g_b2[tid] = bw1[tid] - mean * sc;
    }
}

// ---------------- kernel 4: w1 + stats, software-pipelined ----------------
__global__ __launch_bounds__(256, 3) void k_stats3(
    const int* __restrict__ idx,
    const float* __restrict__ Wp2, const float* __restrict__ bp2,
    const float* __restrict__ Ww1, const float* __restrict__ bww1, int n)
{
    __shared__ __align__(16) float su[8][NSAMP * 68];
    __shared__ __align__(16) float sW1[8 * 68];
    __shared__ float2 sT2[8][2][24];
    __shared__ float red[256], red2[256];

    int tid = threadIdx.x;
    int l = tid & 31, w = tid >> 5;
    int c0 = 2 * l;
    int j = l & 7;

    u64 w20 = *reinterpret_cast<const u64*>(Wp2 + 0*CH + c0);
    u64 w21 = *reinterpret_cast<const u64*>(Wp2 + 1*CH + c0);
    u64 w22 = *reinterpret_cast<const u64*>(Wp2 + 2*CH + c0);
    float2 b2p = *reinterpret_cast<const float2*>(bp2 + c0);
    float2 s2v = make_float2(g_s2[c0], g_s2[c0+1]);
    float2 b2v = make_float2(g_b2[c0], g_b2[c0+1]);
    float bwj = bww1[j];

    for (int i = tid; i < CH * CWD; i += 256) {
        int c = i >> 3, jj = i & 7;
        sW1[jj * 68 + c] = Ww1[c * 8 + jj];
    }
    __syncthreads();

    float sw = 0.f, sq = 0.f;
    int stride = gridDim.x * 8;
    int pt = blockIdx.x * 8 + w;
    u64 pre[NSAMP];
    float2 xq = make_float2(0.f, 0.f);
    int buf = 0;

    if (pt < n) {
        const int4* ip4 = reinterpret_cast<const int4*>(idx + pt * NSAMP);
        int jarr[NSAMP];
        #pragma unroll
        for (int t4 = 0; t4 < 4; t4++) {
            int4 v = ip4[t4];
            jarr[t4*4+0] = v.x; jarr[t4*4+1] = v.y; jarr[t4*4+2] = v.z; jarr[t4*4+3] = v.w;
        }
        #pragma unroll
        for (int t = 0; t < NSAMP; t++)
            pre[t] = *reinterpret_cast<const u64*>(g_xk + (size_t)jarr[t] * CH + c0);
        xq = *reinterpret_cast<const float2*>(g_xq + (size_t)pt * CH + c0);
        if (l < 24)
            sT2[w][0][l] = reinterpret_cast<const float2*>(g_T + (size_t)pt * 48)[l];
    }

    for (; pt < n; pt += stride) {
        int ptn = pt + stride;
        u64 base2 = pk2(b2p.x - xq.x, b2p.y - xq.y);
        __syncwarp();
        const float* tp = reinterpret_cast<const float*>(&sT2[w][buf][0]);

        // phase 1: consume prefetched xk -> u in smem
        #pragma unroll
        for (int t = 0; t < NSAMP; t++) {
            u64 acc = base2;
            acc = ffma2(pk2(tp[3*t+0], tp[3*t+0]), w20, acc);
            acc = ffma2(pk2(tp[3*t+1], tp[3*t+1]), w21, acc);
            acc = ffma2(pk2(tp[3*t+2], tp[3*t+2]), w22, acc);
            float2 r = upk2(fadd2(pre[t], acc));
            float u0 = fmaxf(0.f, fmaf(s2v.x, r.x, b2v.x));
            float u1 = fmaxf(0.f, fmaf(s2v.y, r.y, b2v.y));
            *reinterpret_cast<float2*>(&su[w][t * 68 + c0]) = make_float2(u0, u1);
        }

        // issue next point's loads (land during the dot phase)
        if (ptn < n) {
            const int4* ip4 = reinterpret_cast<const int4*>(idx + ptn * NSAMP);
            int jarr[NSAMP];
            #pragma unroll
            for (int t4 = 0; t4 < 4; t4++) {
                int4 v = ip4[t4];
                jarr[t4*4+0] = v.x; jarr[t4*4+1] = v.y; jarr[t4*4+2] = v.z; jarr[t4*4+3] = v.w;
            }
            #pragma unroll
            for (int t = 0; t < NSAMP; t++)
                pre[t] = *reinterpret_cast<const u64*>(g_xk + (size_t)jarr[t] * CH + c0);
            xq = *reinterpret_cast<const float2*>(g_xq + (size_t)ptn * CH + c0);
            if (l < 24)
                sT2[w][buf ^ 1][l] = reinterpret_cast<const float2*>(g_T + (size_t)ptn * 48)[l];
        }
        __syncwarp();

        // phase 2: 64 -> 8 dot
        #pragma unroll
        for (int k = 0; k < 4; k++) {
            int id = l + 32 * k;
            int t  = id >> 3;
            const ulonglong2* up = reinterpret_cast<const ulonglong2*>(&su[w][t * 68]);
            const ulonglong2* wp = reinterpret_cast<const ulonglong2*>(&sW1[j * 68]);
            u64 a2 = 0ull, b2 = 0ull;
            #pragma unroll
            for (int c = 0; c < 16; c++) {
                ulonglong2 u2 = up[c];
                ulonglong2 v2 = wp[c];
                a2 = ffma2(u2.x, v2.x, a2);
                b2 = ffma2(u2.y, v2.y, b2);
            }
            float2 ab = upk2(fadd2(a2, b2));
            float w1 = ab.x + ab.y + bwj;
            g_w1[(size_t)pt * 128 + id] = w1;
            sw += w1;
            sq += w1 * w1;
        }
        buf ^= 1;
    }

    red[tid] = sw; red2[tid] = sq;
    __syncthreads();
    if (tid < 8) {
        float a = 0.f, b = 0.f;
        for (int k = 0; k < 32; k++) { a += red[k * 8 + tid]; b += red2[k * 8 + tid]; }
        g_part3[blockIdx.x * 16 + tid]     = a;
        g_part3[blockIdx.x * 16 + 8 + tid] = b;
    }
}

// ---------------- finalize 3 ----------------
__global__ __launch_bounds__(256) void k_fin3(
    const float* __restrict__ gw2, const float* __restrict__ bw2, int n)
{
    __shared__ float acc[16][16];
    int tid = threadIdx.x;
    int q = tid & 15, s = tid >> 4;
    float a = 0.f;
    for (int b = s; b < G3; b += 16) a += g_part3[b * 16 + q];
    acc[q][s] = a;
    __syncthreads();
    if (tid < 8) {
        float sum = 0.f, ssq = 0.f;
        for (int k = 0; k < 16; k++) { sum += acc[tid][k]; ssq += acc[8 + tid][k]; }
        float M = (float)n * NSAMP;
        float mean = sum / M;
        float var  = ssq / M - mean * mean;
        float sc = gw2[tid] * rsqrtf(var + EPS);
        g_s3[tid] = sc;
        g_b3[tid] = bw2[tid] - mean * sc;
    }
}

// ---------------- kernel 5: attention weights + weighted sum ----------------
__global__ __launch_bounds__(256, 3) void k_final(
    const int* __restrict__ idx,
    const float* __restrict__ Wp2, const float* __restrict__ bp2,
    const float* __restrict__ Ww2, const float* __restrict__ bww2,
    float* __restrict__ out, int n)
{
    __shared__ float2 sT2[8][24];
    __shared__ __align__(16) float swt[8][NSAMP * 8];

    int tid = threadIdx.x;
    int l = tid & 31, w = tid >> 5;
    int c0 = 2 * l;
    int j = l & 7;
    int base = l & ~7;
    int i0 = c0 & 7;

    u64 w20 = *reinterpret_cast<const u64*>(Wp2 + 0*CH + c0);
    u64 w21 = *reinterpret_cast<const u64*>(Wp2 + 1*CH + c0);
    u64 w22 = *reinterpret_cast<const u64*>(Wp2 + 2*CH + c0);
    float2 b2pf = *reinterpret_cast<const float2*>(bp2 + c0);
    u64 bv2 = pk2(b2pf.x, b2pf.y);
    float s3j = g_s3[j], b3j = g_b3[j];
    float bw2j = bww2[j];
    float ww2c[8];
    #pragma unroll
    for (int kk = 0; kk < 8; kk++) ww2c[kk] = Ww2[kk * 8 + j];

    int warpsTotal = gridDim.x * 8;
    for (int pt = blockIdx.x * 8 + w; pt < n; pt += warpsTotal) {
        // issue xv gathers FIRST; they land during the w/softmax phase
        int jarr[NSAMP];
        {
            const int4* ip4 = reinterpret_cast<const int4*>(idx + pt * NSAMP);
            #pragma unroll
            for (int t4 = 0; t4 < 4; t4++) {
                int4 v = ip4[t4];
                jarr[t4*4+0] = v.x; jarr[t4*4+1] = v.y; jarr[t4*4+2] = v.z; jarr[t4*4+3] = v.w;
            }
        }
        u64 xvreg[NSAMP];
        #pragma unroll
        for (int t = 0; t < NSAMP; t++)
            xvreg[t] = *reinterpret_cast<const u64*>(g_xv + (size_t)jarr[t] * CH + c0);
        if (l < 24)
            sT2[w][l] = reinterpret_cast<const float2*>(g_T + (size_t)pt * 48)[l];

        // w1 -> BN3/ReLU -> 8x8 linear via shuffles
        float wv[4];
        #pragma unroll
        for (int k = 0; k < 4; k++) {
            float w1 = g_w1[(size_t)pt * 128 + l + 32 * k];
            float r = fmaxf(0.f, fmaf(s3j, w1, b3j));
            float wacc = bw2j;
            #pragma unroll
            for (int kk = 0; kk < 8; kk++) {
                float rk = __shfl_sync(0xffffffffu, r, base + kk);
                wacc = fmaf(rk, ww2c[kk], wacc);
            }
            wv[k] = wacc;
        }

        // softmax over 16 neighbors
        float m = fmaxf(fmaxf(wv[0], wv[1]), fmaxf(wv[2], wv[3]));
        m = fmaxf(m, __shfl_xor_sync(0xffffffffu, m, 8));
        m = fmaxf(m, __shfl_xor_sync(0xffffffffu, m, 16));
        float e0 = __expf(wv[0] - m), e1 = __expf(wv[1] - m);
        float e2 = __expf(wv[2] - m), e3 = __expf(wv[3] - m);
        float s = e0 + e1 + e2 + e3;
        s += __shfl_xor_sync(0xffffffffu, s, 8);
        s += __shfl_xor_sync(0xffffffffu, s, 16);
        float inv = 1.f / s;
        int tb = l >> 3;
        swt[w][(tb + 0) * 8 + j]  = e0 * inv;
        swt[w][(tb + 4) * 8 + j]  = e1 * inv;
        swt[w][(tb + 8) * 8 + j]  = e2 * inv;
        swt[w][(tb + 12) * 8 + j] = e3 * inv;
        __syncwarp();

        // out[c] = sum_t (xv_g + p_r) * w
        u64 o2 = 0ull;
        const float* tp = reinterpret_cast<const float*>(&sT2[w][0]);
        #pragma unroll
        for (int t = 0; t < NSAMP; t++) {
            u64 acc = bv2;
            acc = ffma2(pk2(tp[3*t+0], tp[3*t+0]), w20, acc);
            acc = ffma2(pk2(tp[3*t+1], tp[3*t+1]), w21, acc);
            acc = ffma2(pk2(tp[3*t+2], tp[3*t+2]), w22, acc);
            u64 vsum = fadd2(xvreg[t], acc);
            u64 wv2 = *reinterpret_cast<const u64*>(&swt[w][t * 8 + i0]);
            o2 = ffma2(vsum, wv2, o2);
        }
        float2 o = upk2(o2);
        *reinterpret_cast<float2*>(out + (size_t)pt * CH + c0) = make_float2(o.x, o.y);
        __syncwarp();
    }
}

// ---------------- launch ----------------
extern "C" void kernel_launch(void* const* d_in, const int* in_sizes, int n_in,
                              void* d_out, int out_size)
{
    const float* p     = (const float*)d_in[0];
    const float* x     = (const float*)d_in[1];
    const int*   idx   = (const int*)  d_in[3];
    const float* Wq    = (const float*)d_in[4];
    const float* bq    = (const float*)d_in[5];
    const float* Wk    = (const float*)d_in[6];
    const float* bk    = (const float*)d_in[7];
    const float* Wv    = (const float*)d_in[8];
    const float* bv    = (const float*)d_in[9];
    const float* Wp1   = (const float*)d_in[10];
    const float* bp1   = (const float*)d_in[11];
    const float* gp    = (const float*)d_in[12];
    const float* betap = (const float*)d_in[13];
    const float* Wp2   = (const float*)d_in[14];
    const float* bp2   = (const float*)d_in[15];
    const float* gw1   = (const float*)d_in[16];
    const float* bw1   = (const float*)d_in[17];
    const float* Ww1   = (const float*)d_in[18];
    const float* bww1  = (const float*)d_in[19];
    const float* gw2   = (const float*)d_in[20];
    const float* bw2   = (const float*)d_in[21];
    const float* Ww2   = (const float*)d_in[22];
    const float* bww2  = (const float*)d_in[23];

    int n = in_sizes[0] / 3;
    if (n > MAXN) n = MAXN;

    k_qkv<<<(n + 255) / 256, 256>>>(x, Wq, bq, Wk, bk, Wv, bv, n);
    k_stats1<<<G1, 256>>>(p, idx, n);
    k_fin1<<<1, 256>>>(Wp1, bp1, gp, betap, n);
    k_stats2<<<G2, 256>>>(idx, Wp2, bp2, n);
    k_fin2<<<1, 512>>>(gw1, bw1, n);
    k_stats3<<<G3, 256>>>(idx, Wp2, bp2, Ww1, bww1, n);
    k_fin3<<<1, 256>>>(gw2, bw2, n);
    k_final<<<GF, 256>>>(idx, Wp2, bp2, Ww2, bww2, (float*)d_out, n);
}

// round 5
// speedup vs baseline: 1.1902x; 1.1902x over previous
#include <cuda_runtime.h>

#define NSAMP 16
#define CH 64
#define CWD 8
#define EPS 1e-5f
#define MAXN 100000

#define G1 1024
#define G2 1184
#define G3 1184
#define GF 1184

typedef unsigned long long u64;

// ---------------- f32x2 helpers (sm_100+) ----------------
__device__ __forceinline__ u64 pk2(float lo, float hi) {
    u64 r; asm("mov.b64 %0,{%1,%2};" : "=l"(r) : "f"(lo), "f"(hi)); return r;
}
__device__ __forceinline__ float2 upk2(u64 v) {
    float2 f; asm("mov.b64 {%0,%1},%2;" : "=f"(f.x), "=f"(f.y) : "l"(v)); return f;
}
__device__ __forceinline__ u64 ffma2(u64 a, u64 b, u64 c) {
    u64 d; asm("fma.rn.f32x2 %0,%1,%2,%3;" : "=l"(d) : "l"(a), "l"(b), "l"(c)); return d;
}
__device__ __forceinline__ u64 fadd2(u64 a, u64 b) {
    u64 d; asm("add.rn.f32x2 %0,%1,%2;" : "=l"(d) : "l"(a), "l"(b)); return d;
}

// ---------------- device scratch ----------------
__device__ float g_xq[MAXN * CH];
__device__ float g_xk[MAXN * CH];
__device__ float g_xv[MAXN * CH];
__device__ float g_pr0[MAXN * NSAMP * 3];
__device__ float g_T[MAXN * NSAMP * 3];
__device__ float g_w1[MAXN * NSAMP * CWD];

__device__ float g_part1[G1 * 9];
__device__ float g_part2[G2 * 128];
__device__ float g_part3[G3 * 16];

__device__ float g_E[9];
__device__ float g_be[3];
__device__ float g_s2[CH];
__device__ float g_b2[CH];
__device__ float g_s3[CWD];
__device__ float g_b3[CWD];

// ---------------- kernel 1: q/k/v GEMMs (f32x2) ----------------
__global__ __launch_bounds__(256) void k_qkv(
    const float* __restrict__ x,
    const float* __restrict__ Wq, const float* __restrict__ bq,
    const float* __restrict__ Wk, const float* __restrict__ bk,
    const float* __restrict__ Wv, const float* __restrict__ bv,
    int n)
{
    __shared__ __align__(16) float sW[CH * CH];
    __shared__ __align__(16) float sb[CH];
    int tid = threadIdx.x;
    int pt  = blockIdx.x * 256 + tid;
    bool valid = pt < n;

    float xr[CH];
    if (valid) {
        const float4* xp = reinterpret_cast<const float4*>(x + (size_t)pt * CH);
        #pragma unroll
        for (int i = 0; i < 16; i++) {
            float4 v = xp[i];
            xr[4*i+0] = v.x; xr[4*i+1] = v.y; xr[4*i+2] = v.z; xr[4*i+3] = v.w;
        }
    }

    for (int m = 0; m < 3; m++) {
        const float* W = (m == 0) ? Wq : (m == 1) ? Wk : Wv;
        const float* b = (m == 0) ? bq : (m == 1) ? bk : bv;
        float* outp    = (m == 0) ? g_xq : (m == 1) ? g_xk : g_xv;

        for (int i = tid; i < CH * CH / 4; i += 256)
            reinterpret_cast<float4*>(sW)[i] = reinterpret_cast<const float4*>(W)[i];
        if (tid < CH) sb[tid] = b[tid];
        __syncthreads();

        if (valid) {
            #pragma unroll
            for (int chnk = 0; chnk < 2; chnk++) {
                int c0 = chnk * 32;
                u64 acc[16];
                const u64* sbp = reinterpret_cast<const u64*>(&sb[c0]);
                #pragma unroll
                for (int i = 0; i < 16; i++) acc[i] = sbp[i];
                #pragma unroll 4
                for (int k = 0; k < CH; k++) {
                    u64 xk2 = pk2(xr[k], xr[k]);
                    const ulonglong2* wr = reinterpret_cast<const ulonglong2*>(&sW[k * CH + c0]);
                    #pragma unroll
                    for (int cc = 0; cc < 8; cc++) {
                        ulonglong2 w2 = wr[cc];
                        acc[2*cc+0] = ffma2(xk2, w2.x, acc[2*cc+0]);
                        acc[2*cc+1] = ffma2(xk2, w2.y, acc[2*cc+1]);
                    }
                }
                ulonglong2* op = reinterpret_cast<ulonglong2*>(outp + (size_t)pt * CH + c0);
                #pragma unroll
                for (int cc = 0; cc < 8; cc++)
                    op[cc] = make_ulonglong2(acc[2*cc+0], acc[2*cc+1]);
            }
        }
        __syncthreads();
    }
}

// ---------------- kernel 2: mean/cov of p_r0 + materialize p_r0 ----------------
__global__ __launch_bounds__(256) void k_stats1(
    const float* __restrict__ p, const int* __restrict__ idx, int n)
{
    float a[9];
    #pragma unroll
    for (int i = 0; i < 9; i++) a[i] = 0.f;

    int total = n * NSAMP;
    for (int e = blockIdx.x * blockDim.x + threadIdx.x; e < total;
         e += gridDim.x * blockDim.x) {
        int pt = e >> 4;
        int j  = idx[e];
        float dx = p[j*3+0] - p[pt*3+0];
        float dy = p[j*3+1] - p[pt*3+1];
        float dz = p[j*3+2] - p[pt*3+2];
        g_pr0[e*3+0] = dx; g_pr0[e*3+1] = dy; g_pr0[e*3+2] = dz;
        a[0] += dx;     a[1] += dy;     a[2] += dz;
        a[3] += dx*dx;  a[4] += dy*dy;  a[5] += dz*dz;
        a[6] += dx*dy;  a[7] += dx*dz;  a[8] += dy*dz;
    }

    __shared__ float sm[9][256];
    int tid = threadIdx.x;
    #pragma unroll
    for (int i = 0; i < 9; i++) sm[i][tid] = a[i];
    __syncthreads();
    for (int s = 128; s > 0; s >>= 1) {
        if (tid < s) {
            #pragma unroll
            for (int i = 0; i < 9; i++) sm[i][tid] += sm[i][tid + s];
        }
        __syncthreads();
    }
    if (tid < 9) g_part1[blockIdx.x * 9 + tid] = sm[tid][0];
}

// ---------------- finalize 1 ----------------
__global__ __launch_bounds__(256) void k_fin1(
    const float* __restrict__ Wp1, const float* __restrict__ bp1,
    const float* __restrict__ gp,  const float* __restrict__ betap, int n)
{
    __shared__ float ssum[9][16];
    int tid = threadIdx.x;
    if (tid < 144) {
        int q = tid / 16, s = tid % 16;
        float a = 0.f;
        for (int b = s; b < G1; b += 16) a += g_part1[b * 9 + q];
        ssum[q][s] = a;
    }
    __syncthreads();
    if (tid == 0) {
        float S[9];
        #pragma unroll
        for (int q = 0; q < 9; q++) {
            float a = 0.f;
            for (int s = 0; s < 16; s++) a += ssum[q][s];
            S[q] = a;
        }
        float M  = (float)n * NSAMP;
        float m0 = S[0]/M, m1 = S[1]/M, m2 = S[2]/M;
        float C00 = S[3]/M - m0*m0, C11 = S[4]/M - m1*m1, C22 = S[5]/M - m2*m2;
        float C01 = S[6]/M - m0*m1, C02 = S[7]/M - m0*m2, C12 = S[8]/M - m1*m2;
        for (int j = 0; j < 3; j++) {
            float w0 = Wp1[0*3+j], w1 = Wp1[1*3+j], w2 = Wp1[2*3+j];
            float mean = m0*w0 + m1*w1 + m2*w2 + bp1[j];
            float var  = w0*w0*C00 + w1*w1*C11 + w2*w2*C22
                       + 2.f*(w0*w1*C01 + w0*w2*C02 + w1*w2*C12);
            float sc = gp[j] * rsqrtf(var + EPS);
            g_E[0*3+j] = w0 * sc;
            g_E[1*3+j] = w1 * sc;
            g_E[2*3+j] = w2 * sc;
            g_be[j] = (bp1[j] - mean) * sc + betap[j];
        }
    }
}

// ---------------- kernel 3: stats of r_qk + compute/store T (fused, validated 59.5us) ----------------
__global__ __launch_bounds__(256, 3) void k_stats2(
    const int* __restrict__ idx,
    const float* __restrict__ Wp2, const float* __restrict__ bp2, int n)
{
    __shared__ float sT[8][48];
    int tid = threadIdx.x;
    int l = tid & 31, w = tid >> 5;
    int c0 = 2 * l;

    float E[9], be[3];
    #pragma unroll
    for (int i = 0; i < 9; i++) E[i] = g_E[i];
    #pragma unroll
    for (int i = 0; i < 3; i++) be[i] = g_be[i];

    u64 w20 = *reinterpret_cast<const u64*>(Wp2 + 0*CH + c0);
    u64 w21 = *reinterpret_cast<const u64*>(Wp2 + 1*CH + c0);
    u64 w22 = *reinterpret_cast<const u64*>(Wp2 + 2*CH + c0);
    float2 b2p = *reinterpret_cast<const float2*>(bp2 + c0);

    u64 sacc = 0ull, qacc = 0ull;
    int warpsTotal = gridDim.x * 8;
    for (int pt = blockIdx.x * 8 + w; pt < n; pt += warpsTotal) {
        int jarr[NSAMP];
        {
            const int4* ip4 = reinterpret_cast<const int4*>(idx + pt * NSAMP);
            #pragma unroll
            for (int t4 = 0; t4 < 4; t4++) {
                int4 v = ip4[t4];
                jarr[t4*4+0] = v.x; jarr[t4*4+1] = v.y; jarr[t4*4+2] = v.z; jarr[t4*4+3] = v.w;
            }
        }
        u64 pre[NSAMP];
        #pragma unroll
        for (int t = 0; t < NSAMP; t++)
            pre[t] = *reinterpret_cast<const u64*>(g_xk + (size_t)jarr[t] * CH + c0);

        float2 xq = *reinterpret_cast<const float2*>(g_xq + (size_t)pt * CH + c0);
        u64 base2 = pk2(b2p.x - xq.x, b2p.y - xq.y);

        if (l < NSAMP) {
            size_t e = (size_t)pt * NSAMP + l;
            float dx = g_pr0[e*3+0], dy = g_pr0[e*3+1], dz = g_pr0[e*3+2];
            float t0 = fmaxf(0.f, dx*E[0] + dy*E[3] + dz*E[6] + be[0]);
            float t1 = fmaxf(0.f, dx*E[1] + dy*E[4] + dz*E[7] + be[1]);
            float t2 = fmaxf(0.f, dx*E[2] + dy*E[5] + dz*E[8] + be[2]);
            sT[w][l*3+0] = t0; sT[w][l*3+1] = t1; sT[w][l*3+2] = t2;
            g_T[e*3+0] = t0; g_T[e*3+1] = t1; g_T[e*3+2] = t2;
        }
        __syncwarp();
        const float* tp = &sT[w][0];
        #pragma unroll
        for (int t = 0; t < NSAMP; t++) {
            u64 acc = base2;
            acc = ffma2(pk2(tp[3*t+0], tp[3*t+0]), w20, acc);
            acc = ffma2(pk2(tp[3*t+1], tp[3*t+1]), w21, acc);
            acc = ffma2(pk2(tp[3*t+2], tp[3*t+2]), w22, acc);
            u64 r2 = fadd2(pre[t], acc);
            sacc = fadd2(sacc, r2);
            qacc = ffma2(r2, r2, qacc);
        }
        __syncwarp();
    }

    __shared__ float ss[8][64], sq[8][64];
    float2 sf = upk2(sacc), qf = upk2(qacc);
    ss[w][c0] = sf.x; ss[w][c0+1] = sf.y;
    sq[w][c0] = qf.x; sq[w][c0+1] = qf.y;
    __syncthreads();
    if (tid < 64) {
        float a = 0.f, b = 0.f;
        #pragma unroll
        for (int ww = 0; ww < 8; ww++) { a += ss[ww][tid]; b += sq[ww][tid]; }
        g_part2[blockIdx.x * 128 + tid]      = a;
        g_part2[blockIdx.x * 128 + 64 + tid] = b;
    }
}

// ---------------- finalize 2 ----------------
__global__ __launch_bounds__(512) void k_fin2(
    const float* __restrict__ gw1, const float* __restrict__ bw1, int n)
{
    __shared__ float acc[4][128];
    int tid = threadIdx.x;
    int q = tid & 127, s = tid >> 7;
    float a = 0.f;
    for (int b = s; b < G2; b += 4) a += g_part2[b * 128 + q];
    acc[s][q] = a;
    __syncthreads();
    if (tid < 64) {
        float sum = acc[0][tid] + acc[1][tid] + acc[2][tid] + acc[3][tid];
        float ssq = acc[0][64+tid] + acc[1][64+tid] + acc[2][64+tid] + acc[3][64+tid];
        float M = (float)n * NSAMP;
        float mean = sum / M;
        float var  = ssq / M - mean * mean;
        float sc = gw1[tid] * rsqrtf(var + EPS);
        g_s2[tid] = sc;
        g_b2[tid] = bw1[tid] - mean * sc;
    }
}

// ---------------- kernel 4: w1 + stats (R3 form, no reg prefetch) ----------------
__global__ __launch_bounds__(256) void k_stats3(
    const int* __restrict__ idx,
    const float* __restrict__ Wp2, const float* __restrict__ bp2,
    const float* __restrict__ Ww1, const float* __restrict__ bww1, int n)
{
    __shared__ __align__(16) float su[8][NSAMP * 68];
    __shared__ __align__(16) float sW1[8 * 68];
    __shared__ float2 sT2[8][24];
    __shared__ float red[256], red2[256];

    int tid = threadIdx.x;
    int l = tid & 31, w = tid >> 5;
    int c0 = 2 * l;
    int j = l & 7;

    u64 w20 = *reinterpret_cast<const u64*>(Wp2 + 0*CH + c0);
    u64 w21 = *reinterpret_cast<const u64*>(Wp2 + 1*CH + c0);
    u64 w22 = *reinterpret_cast<const u64*>(Wp2 + 2*CH + c0);
    float2 b2p = *reinterpret_cast<const float2*>(bp2 + c0);
    float2 s2v = make_float2(g_s2[c0], g_s2[c0+1]);
    float2 b2v = make_float2(g_b2[c0], g_b2[c0+1]);
    float bwj = bww1[j];

    for (int i = tid; i < CH * CWD; i += 256) {
        int c = i >> 3, jj = i & 7;
        sW1[jj * 68 + c] = Ww1[c * 8 + jj];
    }
    __syncthreads();

    float sw = 0.f, sq = 0.f;
    int warpsTotal = gridDim.x * 8;
    for (int pt = blockIdx.x * 8 + w; pt < n; pt += warpsTotal) {
        float2 xq = *reinterpret_cast<const float2*>(g_xq + (size_t)pt * CH + c0);
        u64 base2 = pk2(b2p.x - xq.x, b2p.y - xq.y);
        if (l < 24)
            sT2[w][l] = reinterpret_cast<const float2*>(g_T + (size_t)pt * 48)[l];
        int jarr[NSAMP];
        {
            const int4* ip4 = reinterpret_cast<const int4*>(idx + pt * NSAMP);
            #pragma unroll
            for (int t4 = 0; t4 < 4; t4++) {
                int4 v = ip4[t4];
                jarr[t4*4+0] = v.x; jarr[t4*4+1] = v.y; jarr[t4*4+2] = v.z; jarr[t4*4+3] = v.w;
            }
        }
        __syncwarp();
        const float* tp = reinterpret_cast<const float*>(&sT2[w][0]);
        #pragma unroll
        for (int t = 0; t < NSAMP; t++) {
            u64 acc = base2;
            acc = ffma2(pk2(tp[3*t+0], tp[3*t+0]), w20, acc);
            acc = ffma2(pk2(tp[3*t+1], tp[3*t+1]), w21, acc);
            acc = ffma2(pk2(tp[3*t+2], tp[3*t+2]), w22, acc);
            u64 xk2 = *reinterpret_cast<const u64*>(g_xk + (size_t)jarr[t] * CH + c0);
            float2 r = upk2(fadd2(xk2, acc));
            float u0 = fmaxf(0.f, fmaf(s2v.x, r.x, b2v.x));
            float u1 = fmaxf(0.f, fmaf(s2v.y, r.y, b2v.y));
            *reinterpret_cast<float2*>(&su[w][t * 68 + c0]) = make_float2(u0, u1);
        }
        __syncwarp();
        #pragma unroll
        for (int k = 0; k < 4; k++) {
            int id = l + 32 * k;
            int t  = id >> 3;
            const ulonglong2* up = reinterpret_cast<const ulonglong2*>(&su[w][t * 68]);
            const ulonglong2* wp = reinterpret_cast<const ulonglong2*>(&sW1[j * 68]);
            u64 a2 = 0ull, b2 = 0ull;
            #pragma unroll
            for (int c = 0; c < 16; c++) {
                ulonglong2 u2 = up[c];
                ulonglong2 v2 = wp[c];
                a2 = ffma2(u2.x, v2.x, a2);
                b2 = ffma2(u2.y, v2.y, b2);
            }
            float2 ab = upk2(fadd2(a2, b2));
            float w1 = ab.x + ab.y + bwj;
            g_w1[(size_t)pt * 128 + id] = w1;
            sw += w1;
            sq += w1 * w1;
        }
        __syncwarp();
    }

    red[tid] = sw; red2[tid] = sq;
    __syncthreads();
    if (tid < 8) {
        float a = 0.f, b = 0.f;
        for (int k = 0; k < 32; k++) { a += red[k * 8 + tid]; b += red2[k * 8 + tid]; }
        g_part3[blockIdx.x * 16 + tid]     = a;
        g_part3[blockIdx.x * 16 + 8 + tid] = b;
    }
}

// ---------------- finalize 3 ----------------
__global__ __launch_bounds__(256) void k_fin3(
    const float* __restrict__ gw2, const float* __restrict__ bw2, int n)
{
    __shared__ float acc[16][16];
    int tid = threadIdx.x;
    int q = tid & 15, s = tid >> 4;
    float a = 0.f;
    for (int b = s; b < G3; b += 16) a += g_part3[b * 16 + q];
    acc[q][s] = a;
    __syncthreads();
    if (tid < 8) {
        float sum = 0.f, ssq = 0.f;
        for (int k = 0; k < 16; k++) { sum += acc[tid][k]; ssq += acc[8 + tid][k]; }
        float M = (float)n * NSAMP;
        float mean = sum / M;
        float var  = ssq / M - mean * mean;
        float sc = gw2[tid] * rsqrtf(var + EPS);
        g_s3[tid] = sc;
        g_b3[tid] = bw2[tid] - mean * sc;
    }
}

// ---------------- kernel 5: attention weights + weighted sum (R3 form) ----------------
__global__ __launch_bounds__(256) void k_final(
    const int* __restrict__ idx,
    const float* __restrict__ Wp2, const float* __restrict__ bp2,
    const float* __restrict__ Ww2, const float* __restrict__ bww2,
    float* __restrict__ out, int n)
{
    __shared__ float2 sT2[8][24];
    __shared__ __align__(16) float swt[8][NSAMP * 8];

    int tid = threadIdx.x;
    int l = tid & 31, w = tid >> 5;
    int c0 = 2 * l;
    int j = l & 7;
    int base = l & ~7;
    int i0 = c0 & 7;

    u64 w20 = *reinterpret_cast<const u64*>(Wp2 + 0*CH + c0);
    u64 w21 = *reinterpret_cast<const u64*>(Wp2 + 1*CH + c0);
    u64 w22 = *reinterpret_cast<const u64*>(Wp2 + 2*CH + c0);
    float2 b2pf = *reinterpret_cast<const float2*>(bp2 + c0);
    u64 bv2 = pk2(b2pf.x, b2pf.y);
    float s3j = g_s3[j], b3j = g_b3[j];
    float bw2j = bww2[j];
    float ww2c[8];
    #pragma unroll
    for (int kk = 0; kk < 8; kk++) ww2c[kk] = Ww2[kk * 8 + j];

    int warpsTotal = gridDim.x * 8;
    for (int pt = blockIdx.x * 8 + w; pt < n; pt += warpsTotal) {
        if (l < 24)
            sT2[w][l] = reinterpret_cast<const float2*>(g_T + (size_t)pt * 48)[l];
        int jarr[NSAMP];
        {
            const int4* ip4 = reinterpret_cast<const int4*>(idx + pt * NSAMP);
            #pragma unroll
            for (int t4 = 0; t4 < 4; t4++) {
                int4 v = ip4[t4];
                jarr[t4*4+0] = v.x; jarr[t4*4+1] = v.y; jarr[t4*4+2] = v.z; jarr[t4*4+3] = v.w;
            }
        }

        float wv[4];
        #pragma unroll
        for (int k = 0; k < 4; k++) {
            float w1 = g_w1[(size_t)pt * 128 + l + 32 * k];
            float r = fmaxf(0.f, fmaf(s3j, w1, b3j));
            float wacc = bw2j;
            #pragma unroll
            for (int kk = 0; kk < 8; kk++) {
                float rk = __shfl_sync(0xffffffffu, r, base + kk);
                wacc = fmaf(rk, ww2c[kk], wacc);
            }
            wv[k] = wacc;
        }

        float m = fmaxf(fmaxf(wv[0], wv[1]), fmaxf(wv[2], wv[3]));
        m = fmaxf(m, __shfl_xor_sync(0xffffffffu, m, 8));
        m = fmaxf(m, __shfl_xor_sync(0xffffffffu, m, 16));
        float e0 = __expf(wv[0] - m), e1 = __expf(wv[1] - m);
        float e2 = __expf(wv[2] - m), e3 = __expf(wv[3] - m);
        float s = e0 + e1 + e2 + e3;
        s += __shfl_xor_sync(0xffffffffu, s, 8);
        s += __shfl_xor_sync(0xffffffffu, s, 16);
        float inv = 1.f / s;
        int tb = l >> 3;
        swt[w][(tb + 0) * 8 + j]  = e0 * inv;
        swt[w][(tb + 4) * 8 + j]  = e1 * inv;
        swt[w][(tb + 8) * 8 + j]  = e2 * inv;
        swt[w][(tb + 12) * 8 + j] = e3 * inv;
        __syncwarp();

        u64 o2 = 0ull;
        const float* tp = reinterpret_cast<const float*>(&sT2[w][0]);
        #pragma unroll
        for (int t = 0; t < NSAMP; t++) {
            u64 acc = bv2;
            acc = ffma2(pk2(tp[3*t+0], tp[3*t+0]), w20, acc);
            acc = ffma2(pk2(tp[3*t+1], tp[3*t+1]), w21, acc);
            acc = ffma2(pk2(tp[3*t+2], tp[3*t+2]), w22, acc);
            u64 xv2 = *reinterpret_cast<const u64*>(g_xv + (size_t)jarr[t] * CH + c0);
            u64 vsum = fadd2(xv2, acc);
            u64 wv2 = *reinterpret_cast<const u64*>(&swt[w][t * 8 + i0]);
            o2 = ffma2(vsum, wv2, o2);
        }
        float2 o = upk2(o2);
        *reinterpret_cast<float2*>(out + (size_t)pt * CH + c0) = make_float2(o.x, o.y);
        __syncwarp();
    }
}

// ---------------- launch ----------------
extern "C" void kernel_launch(void* const* d_in, const int* in_sizes, int n_in,
                              void* d_out, int out_size)
{
    const float* p     = (const float*)d_in[0];
    const float* x     = (const float*)d_in[1];
    const int*   idx   = (const int*)  d_in[3];
    const float* Wq    = (const float*)d_in[4];
    const float* bq    = (const float*)d_in[5];
    const float* Wk    = (const float*)d_in[6];
    const float* bk    = (const float*)d_in[7];
    const float* Wv    = (const float*)d_in[8];
    const float* bv    = (const float*)d_in[9];
    const float* Wp1   = (const float*)d_in[10];
    const float* bp1   = (const float*)d_in[11];
    const float* gp    = (const float*)d_in[12];
    const float* betap = (const float*)d_in[13];
    const float* Wp2   = (const float*)d_in[14];
    const float* bp2   = (const float*)d_in[15];
    const float* gw1   = (const float*)d_in[16];
    const float* bw1   = (const float*)d_in[17];
    const float* Ww1   = (const float*)d_in[18];
    const float* bww1  = (const float*)d_in[19];
    const float* gw2   = (const float*)d_in[20];
    const float* bw2   = (const float*)d_in[21];
    const float* Ww2   = (const float*)d_in[22];
    const float* bww2  = (const float*)d_in[23];

    int n = in_sizes[0] / 3;
    if (n > MAXN) n = MAXN;

    k_qkv<<<(n + 255) / 256, 256>>>(x, Wq, bq, Wk, bk, Wv, bv, n);
    k_stats1<<<G1, 256>>>(p, idx, n);
    k_fin1<<<1, 256>>>(Wp1, bp1, gp, betap, n);
    k_stats2<<<G2, 256>>>(idx, Wp2, bp2, n);
    k_fin2<<<1, 512>>>(gw1, bw1, n);
    k_stats3<<<G3, 256>>>(idx, Wp2, bp2, Ww1, bww1, n);
    k_fin3<<<1, 256>>>(gw2, bw2, n);
    k_final<<<GF, 256>>>(idx, Wp2, bp2, Ww2, bww2, (float*)d_out, n);
}